// round 13
// baseline (speedup 1.0000x reference)
#include <cuda_runtime.h>
#include <cstdint>

#define N_NODES  100000
#define N_EDGES  1600000
#define IN_CH    128
#define HID      64
#define N_GRAPHS 64
#define OUT_CH   10
#define SCAN_BLOCKS ((N_NODES + 255) / 256)   // 391

// ---------------- scratch (zero-initialized at load; state-cycled per call) -------
__device__ float g_dinv[N_NODES];
__device__ float g_xw [(size_t)N_NODES * HID];
__device__ float g_h  [(size_t)N_NODES * HID];
__device__ float g_pool[N_GRAPHS * HID];          // zeroed by final_kernel after use
__device__ int   g_is64;

__device__ __align__(16) int g_cnt_i[N_NODES];    // zeroed by gather_kernel after scan
__device__ int g_rowstart[N_NODES + 1];
__device__ int g_cursor[N_NODES];
__device__ unsigned long long g_pkt[SCAN_BLOCKS]; // zeroed by gather_kernel after scan

struct __align__(8) Edge { int r; float w; };
__device__ Edge g_edges[N_EDGES];

// ---------------- f32x2 helpers ----------------
__device__ __forceinline__ unsigned long long pk2(float a, float b) {
    unsigned long long r;
    asm("mov.b64 %0, {%1, %2};" : "=l"(r) : "f"(a), "f"(b));
    return r;
}
__device__ __forceinline__ void fma2(unsigned long long& d,
                                     unsigned long long a, unsigned long long b) {
    asm("fma.rn.f32x2 %0, %1, %2, %0;" : "+l"(d) : "l"(a), "l"(b));
}
__device__ __forceinline__ float2 upk2(unsigned long long v) {
    float2 f;
    asm("mov.b64 {%0, %1}, %2;" : "=f"(f.x), "=f"(f.y) : "l"(v));
    return f;
}

// ---------------- index dtype helper ----------------
__device__ __forceinline__ long long ld_idx(const void* p, long long i, int is64) {
    if (is64) return ((const long long*)p)[i];
    return (long long)((const int*)p)[i];
}

__device__ __forceinline__ void ld_idx4(const void* p, long long base_elem, int is64, int out[4]) {
    if (is64) {
        const longlong2* q = (const longlong2*)((const long long*)p + base_elem);
        longlong2 a = q[0];
        longlong2 b = q[1];
        out[0] = (int)a.x; out[1] = (int)a.y; out[2] = (int)b.x; out[3] = (int)b.y;
    } else {
        int4 a = *(const int4*)((const int*)p + base_elem);
        out[0] = a.x; out[1] = a.y; out[2] = a.z; out[3] = a.w;
    }
}

// ---------------- 0: in-degree count (+local is64 detect; cnt_i pre-zeroed) ------
__global__ void __launch_bounds__(256) count_kernel(const void* ei) {
    __shared__ int s_is64;
    if (threadIdx.x < 32) {
        const long long* p = (const long long*)ei;
        long long v = p[threadIdx.x];
        unsigned ok = __ballot_sync(0xffffffffu, v >= 0 && v < N_NODES);
        if (threadIdx.x == 0) s_is64 = (ok == 0xffffffffu) ? 1 : 0;
    }
    __syncthreads();
    int is64 = s_is64;
    if (blockIdx.x == 0 && threadIdx.x == 0) {
        g_is64 = is64;
        g_rowstart[N_NODES] = N_EDGES;
    }
    int base = (blockIdx.x * blockDim.x + threadIdx.x) * 4;
    if (base >= N_EDGES) return;
    int c[4];
    ld_idx4(ei, (long long)N_EDGES + base, is64, c);
    #pragma unroll
    for (int q = 0; q < 4; q++) atomicAdd(&g_cnt_i[c[q]], 1);
}

// ---------------- 1: exclusive scan (decoupled lookback; pkt pre-zeroed) + dinv ---
__global__ void __launch_bounds__(256) scan_kernel() {
    __shared__ int sh[256];
    __shared__ int s_prefix;
    int t = threadIdx.x;
    int b = blockIdx.x;
    int i = b * 256 + t;
    int v = (i < N_NODES) ? g_cnt_i[i] : 0;

    sh[t] = v;
    __syncthreads();
    #pragma unroll
    for (int s = 1; s < 256; s <<= 1) {
        int a = (t >= s) ? sh[t - s] : 0;
        __syncthreads();
        sh[t] += a;
        __syncthreads();
    }
    int incl = sh[t];
    int agg = sh[255];

    if (t == 0) {
        __threadfence();
        atomicExch(&g_pkt[b], (1ull << 32) | (unsigned long long)(unsigned)agg);
    }

    if (t < 32) {
        int prefix = 0;
        int idx = b - 1;
        while (idx >= 0) {
            int look = idx - t;
            unsigned long long pkt = 0ull;
            if (look >= 0) {
                do { pkt = atomicAdd(&g_pkt[look], 0ull); } while ((pkt >> 32) == 0ull);
            }
            unsigned incmask = __ballot_sync(0xffffffffu, look >= 0 && (pkt >> 32) == 2ull);
            int val = (int)(unsigned)pkt;
            if (incmask) {
                int firstinc = __ffs(incmask) - 1;
                int contrib = (t <= firstinc) ? val : 0;
                #pragma unroll
                for (int o = 16; o; o >>= 1) contrib += __shfl_down_sync(0xffffffffu, contrib, o);
                prefix += __shfl_sync(0xffffffffu, contrib, 0);
                break;
            } else {
                int contrib = (look >= 0) ? val : 0;
                #pragma unroll
                for (int o = 16; o; o >>= 1) contrib += __shfl_down_sync(0xffffffffu, contrib, o);
                prefix += __shfl_sync(0xffffffffu, contrib, 0);
                idx -= 32;
            }
        }
        if (t == 0) {
            s_prefix = prefix;
            __threadfence();
            atomicExch(&g_pkt[b], (2ull << 32) | (unsigned long long)(unsigned)(prefix + agg));
        }
    }
    __syncthreads();
    int prefix = s_prefix;

    if (i < N_NODES) {
        int start = prefix + incl - v;
        g_rowstart[i] = start;
        g_cursor[i] = start;
        g_dinv[i] = rsqrtf((float)v + 1.0f);
    }
}

// ---------------- 2: fill CSR ----------------
__global__ void __launch_bounds__(256) fill_kernel(const void* ei) {
    int base = (blockIdx.x * blockDim.x + threadIdx.x) * 4;
    if (base >= N_EDGES) return;
    int is64 = g_is64;
    int r[4], c[4];
    ld_idx4(ei, base, is64, r);
    ld_idx4(ei, (long long)N_EDGES + base, is64, c);
    float dr[4], dc[4];
    #pragma unroll
    for (int q = 0; q < 4; q++) { dr[q] = g_dinv[r[q]]; dc[q] = g_dinv[c[q]]; }
    int pos[4];
    #pragma unroll
    for (int q = 0; q < 4; q++) pos[q] = atomicAdd(&g_cursor[c[q]], 1);
    #pragma unroll
    for (int q = 0; q < 4; q++) {
        Edge ed; ed.r = r[q]; ed.w = dr[q] * dc[q];
        g_edges[pos[q]] = ed;
    }
}

// ---------------- GEMM1 (K=128): single smem phase, reg-capped for co-residency ---
// launch_bounds(256,3) caps regs at 85 (smem already limits residency to 2 blocks;
// the cap exists purely so build-kernel blocks can co-reside: 2x256x85=43.5k regs
// leaves 22k regs + 1280 thread slots + 36KB smem per SM for the side stream).
__global__ void __launch_bounds__(256, 3) gemm1_kernel(
        const float* __restrict__ X, const float* __restrict__ W,
        float* __restrict__ Y, int n) {
    extern __shared__ float sm[];
    float* Ws = sm;                 // 128*64
    float* Xs = sm + 128 * 64;      // 128*128
    int t = threadIdx.x;
    int row0 = blockIdx.x * 128;
    int c0 = (t & 15) * 4;
    int r0 = (t >> 4) * 8;

    #pragma unroll
    for (int i = 0; i < 8; i++) {
        int idx = t + i * 256;
        ((float4*)Ws)[idx] = ((const float4*)W)[idx];
    }
    #pragma unroll
    for (int i = 0; i < 16; i++) {
        int idx = t + i * 256;
        int r = idx >> 5, kq = idx & 31;
        int gr = row0 + r;
        float4 v = (gr < n) ? ((const float4*)(X + (size_t)gr * 128))[kq]
                            : make_float4(0.f, 0.f, 0.f, 0.f);
        ((float4*)Xs)[idx] = v;
    }
    __syncthreads();

    unsigned long long a01[8], a23[8];
    #pragma unroll
    for (int r = 0; r < 8; r++) { a01[r] = 0ull; a23[r] = 0ull; }

    #pragma unroll 2
    for (int k = 0; k < 128; k += 4) {
        unsigned long long w01[4], w23[4];
        #pragma unroll
        for (int kk = 0; kk < 4; kk++) {
            float4 wv = *(const float4*)&Ws[(k + kk) * 64 + c0];
            w01[kk] = pk2(wv.x, wv.y);
            w23[kk] = pk2(wv.z, wv.w);
        }
        #pragma unroll
        for (int r = 0; r < 8; r++) {
            float4 xv = *(const float4*)&Xs[(r0 + r) * 128 + k];
            unsigned long long x0 = pk2(xv.x, xv.x);
            fma2(a01[r], x0, w01[0]); fma2(a23[r], x0, w23[0]);
            unsigned long long x1 = pk2(xv.y, xv.y);
            fma2(a01[r], x1, w01[1]); fma2(a23[r], x1, w23[1]);
            unsigned long long x2 = pk2(xv.z, xv.z);
            fma2(a01[r], x2, w01[2]); fma2(a23[r], x2, w23[2]);
            unsigned long long x3 = pk2(xv.w, xv.w);
            fma2(a01[r], x3, w01[3]); fma2(a23[r], x3, w23[3]);
        }
    }

    #pragma unroll
    for (int r = 0; r < 8; r++) {
        int gr = row0 + r0 + r;
        if (gr < n) {
            float2 lo = upk2(a01[r]);
            float2 hi = upk2(a23[r]);
            float4 o; o.x = lo.x; o.y = lo.y; o.z = hi.x; o.w = hi.y;
            *(float4*)&Y[(size_t)gr * 64 + c0] = o;
        }
    }
}

// ---------------- GEMM2 (K=64, static smem, occ 3) ----------------
__global__ void __launch_bounds__(256, 3) gemm2_kernel(
        const float* __restrict__ X, const float* __restrict__ W,
        float* __restrict__ Y, int n) {
    __shared__ float Ws[64 * 64];
    __shared__ float Xs[128 * 64];
    int t = threadIdx.x;
    int row0 = blockIdx.x * 128;
    int c0 = (t & 15) * 4;
    int r0 = (t >> 4) * 8;

    unsigned long long a01[8], a23[8];
    #pragma unroll
    for (int r = 0; r < 8; r++) { a01[r] = 0ull; a23[r] = 0ull; }

    for (int i = t; i < 64 * 16; i += 256) {
        ((float4*)Ws)[i] = ((const float4*)W)[i];
    }
    for (int i = t; i < 128 * 16; i += 256) {
        int r = i >> 4, kq = i & 15;
        int gr = row0 + r;
        float4 v = (gr < n) ? *(const float4*)(X + (size_t)gr * 64 + kq * 4)
                            : make_float4(0.f, 0.f, 0.f, 0.f);
        ((float4*)Xs)[i] = v;
    }
    __syncthreads();

    #pragma unroll 4
    for (int k = 0; k < 64; k += 4) {
        unsigned long long w01[4], w23[4];
        #pragma unroll
        for (int kk = 0; kk < 4; kk++) {
            float4 wv = *(const float4*)&Ws[(k + kk) * 64 + c0];
            w01[kk] = pk2(wv.x, wv.y);
            w23[kk] = pk2(wv.z, wv.w);
        }
        #pragma unroll
        for (int r = 0; r < 8; r++) {
            float4 xv = *(const float4*)&Xs[(r0 + r) * 64 + k];
            unsigned long long x0 = pk2(xv.x, xv.x);
            fma2(a01[r], x0, w01[0]); fma2(a23[r], x0, w23[0]);
            unsigned long long x1 = pk2(xv.y, xv.y);
            fma2(a01[r], x1, w01[1]); fma2(a23[r], x1, w23[1]);
            unsigned long long x2 = pk2(xv.z, xv.z);
            fma2(a01[r], x2, w01[2]); fma2(a23[r], x2, w23[2]);
            unsigned long long x3 = pk2(xv.w, xv.w);
            fma2(a01[r], x3, w01[3]); fma2(a23[r], x3, w23[3]);
        }
    }

    #pragma unroll
    for (int r = 0; r < 8; r++) {
        int gr = row0 + r0 + r;
        if (gr < n) {
            float2 lo = upk2(a01[r]);
            float2 hi = upk2(a23[r]);
            float4 o; o.x = lo.x; o.y = lo.y; o.z = hi.x; o.w = hi.y;
            *(float4*)&Y[(size_t)gr * 64 + c0] = o;
        }
    }
}

// ---------------- gather core ----------------
__device__ __forceinline__ float4 gather_node4(const float* __restrict__ xw,
                                               const float* __restrict__ bias,
                                               int node, int c4) {
    int s = g_rowstart[node];
    int e = g_rowstart[node + 1];
    float dc = g_dinv[node];

    float4 sv = *(const float4*)&xw[(size_t)node * 64 + c4 * 4];
    float sl = dc * dc;
    unsigned long long a01 = pk2(sv.x * sl, sv.y * sl);
    unsigned long long a23 = pk2(sv.z * sl, sv.w * sl);
    unsigned long long b01 = 0ull, b23 = 0ull;

    int j = s;
    for (; j + 4 <= e; j += 4) {
        Edge ed[4];
        #pragma unroll
        for (int q = 0; q < 4; q++) ed[q] = g_edges[j + q];
        float4 v[4];
        #pragma unroll
        for (int q = 0; q < 4; q++)
            v[q] = *(const float4*)&xw[(size_t)ed[q].r * 64 + c4 * 4];
        #pragma unroll
        for (int q = 0; q < 4; q += 2) {
            unsigned long long w0 = pk2(ed[q].w, ed[q].w);
            unsigned long long w1 = pk2(ed[q + 1].w, ed[q + 1].w);
            fma2(a01, pk2(v[q].x,     v[q].y),     w0);
            fma2(a23, pk2(v[q].z,     v[q].w),     w0);
            fma2(b01, pk2(v[q + 1].x, v[q + 1].y), w1);
            fma2(b23, pk2(v[q + 1].z, v[q + 1].w), w1);
        }
    }
    for (; j < e; j++) {
        Edge e0 = g_edges[j];
        float4 v0 = *(const float4*)&xw[(size_t)e0.r * 64 + c4 * 4];
        unsigned long long w0 = pk2(e0.w, e0.w);
        fma2(a01, pk2(v0.x, v0.y), w0);
        fma2(a23, pk2(v0.z, v0.w), w0);
    }

    float2 p01 = upk2(a01), q01 = upk2(b01);
    float2 p23 = upk2(a23), q23 = upk2(b23);
    float4 bv = ((const float4*)bias)[c4];
    float4 r;
    r.x = fmaxf(p01.x + q01.x + bv.x, 0.f);
    r.y = fmaxf(p01.y + q01.y + bv.y, 0.f);
    r.z = fmaxf(p23.x + q23.x + bv.z, 0.f);
    r.w = fmaxf(p23.y + q23.y + bv.w, 0.f);
    return r;
}

// ---------------- gather1 (+state-cycle zeroing of cnt_i / pkt for next replay) ---
__global__ void gather_kernel(const float* __restrict__ xw, const float* __restrict__ bias,
                              float* __restrict__ out) {
    int gid = blockIdx.x * blockDim.x + threadIdx.x;
    if (gid < 25000) ((int4*)g_cnt_i)[gid] = make_int4(0, 0, 0, 0);
    else if (gid - 25000 < SCAN_BLOCKS) g_pkt[gid - 25000] = 0ull;

    int lane = threadIdx.x & 31;
    int node = (gid >> 5) * 2 + (lane >> 4);
    if (node >= N_NODES) return;
    int c4 = lane & 15;
    float4 r = gather_node4(xw, bias, node, c4);
    *(float4*)&out[(size_t)node * 64 + c4 * 4] = r;
}

// ---------------- gather2 + mean-pool ----------------
__global__ void gather_pool_kernel(const float* __restrict__ xw, const float* __restrict__ bias,
                                   const void* batch) {
    int gid = blockIdx.x * blockDim.x + threadIdx.x;
    int lane = threadIdx.x & 31;
    int node = (gid >> 5) * 2 + (lane >> 4);
    if (node >= N_NODES) return;
    int c4 = lane & 15;
    float4 r = gather_node4(xw, bias, node, c4);
    int g = (int)ld_idx(batch, node, g_is64);
    float* dst = &g_pool[g * HID + c4 * 4];
    asm volatile("red.global.add.v4.f32 [%0], {%1,%2,%3,%4};"
                 :: "l"(dst), "f"(r.x), "f"(r.y), "f"(r.z), "f"(r.w) : "memory");
}

// ---------------- final classifier (+re-zero pool for next replay) ----------------
__global__ void final_kernel(const float* __restrict__ Wl, const float* __restrict__ bl,
                             const void* batch, float* __restrict__ out) {
    __shared__ float s_inv;
    int g = blockIdx.x;
    int o = threadIdx.x;
    if (o == 0) {
        int is64 = g_is64;
        int lo0 = 0, hi0 = N_NODES;
        while (lo0 < hi0) { int m = (lo0 + hi0) >> 1;
            if (ld_idx(batch, m, is64) < g) lo0 = m + 1; else hi0 = m; }
        int lo1 = lo0, hi1 = N_NODES;
        while (lo1 < hi1) { int m = (lo1 + hi1) >> 1;
            if (ld_idx(batch, m, is64) < g + 1) lo1 = m + 1; else hi1 = m; }
        float cnt = (float)(lo1 - lo0);
        s_inv = 1.0f / fmaxf(cnt, 1.0f);
    }
    __syncthreads();
    if (o < OUT_CH) {
        float s = 0.0f;
        #pragma unroll
        for (int c = 0; c < HID; c++)
            s += g_pool[g * HID + c] * Wl[c * OUT_CH + o];
        out[g * OUT_CH + o] = s * s_inv + bl[o];
    }
    __syncthreads();
    g_pool[g * HID + o] = 0.0f;
}

// ---------------- launch ----------------
static cudaStream_t s_side = nullptr;
static cudaEvent_t  s_evFork = nullptr;
static cudaEvent_t  s_evJoin = nullptr;

extern "C" void kernel_launch(void* const* d_in, const int* in_sizes, int n_in,
                              void* d_out, int out_size) {
    const float* x  = (const float*)d_in[0];
    const float* W1 = (const float*)d_in[1];
    const float* b1 = (const float*)d_in[2];
    const float* W2 = (const float*)d_in[3];
    const float* b2 = (const float*)d_in[4];
    const float* Wl = (const float*)d_in[5];
    const float* bl = (const float*)d_in[6];
    const void*  ei = d_in[7];
    const void*  batch = d_in[8];
    float* out = (float*)d_out;

    if (!s_side) {
        int lo, hi;
        cudaDeviceGetStreamPriorityRange(&lo, &hi);
        cudaStreamCreateWithPriority(&s_side, cudaStreamNonBlocking, hi);
        cudaEventCreateWithFlags(&s_evFork, cudaEventDisableTiming);
        cudaEventCreateWithFlags(&s_evJoin, cudaEventDisableTiming);
        cudaFuncSetAttribute(gemm1_kernel,
                             cudaFuncAttributeMaxDynamicSharedMemorySize, 96 * 1024);
    }

    float *xw = nullptr, *h = nullptr;
    cudaGetSymbolAddress((void**)&xw, g_xw);
    cudaGetSymbolAddress((void**)&h,  g_h);

    const int T = 256;
    int nb_edges4 = (N_EDGES / 4 + T - 1) / T;
    int nb_gemm   = (N_NODES + 127) / 128;
    int nb_gather = ((N_NODES + 1) / 2 * 32 + T - 1) / T;

    // fork: build on high-priority side stream, GEMM1 on main (now co-resident)
    cudaEventRecord(s_evFork, 0);
    cudaStreamWaitEvent(s_side, s_evFork, 0);

    count_kernel<<<nb_edges4, T, 0, s_side>>>(ei);            // 0
    scan_kernel<<<SCAN_BLOCKS, T, 0, s_side>>>();             // 1
    fill_kernel<<<nb_edges4, T, 0, s_side>>>(ei);             // 2
    cudaEventRecord(s_evJoin, s_side);

    gemm1_kernel<<<nb_gemm, T, 96 * 1024>>>(x, W1, xw, N_NODES);  // 3  <- ncu slot

    cudaStreamWaitEvent(0, s_evJoin, 0);
    gather_kernel<<<nb_gather, T>>>(xw, b1, h);               // 4
    gemm2_kernel<<<nb_gemm, T>>>(h, W2, xw, N_NODES);         // 5
    gather_pool_kernel<<<nb_gather, T>>>(xw, b2, batch);      // 6
    final_kernel<<<N_GRAPHS, 64>>>(Wl, bl, batch, out);       // 7
}

// round 14
// speedup vs baseline: 1.0336x; 1.0336x over previous
#include <cuda_runtime.h>
#include <cstdint>

#define N_NODES  100000
#define N_EDGES  1600000
#define IN_CH    128
#define HID      64
#define N_GRAPHS 64
#define OUT_CH   10
#define SCAN_BLOCKS ((N_NODES + 255) / 256)   // 391

// ---------------- scratch (zero-initialized at load; state-cycled per call) -------
__device__ float g_dinv[N_NODES];
__device__ float g_xw [(size_t)N_NODES * HID];
__device__ float g_h  [(size_t)N_NODES * HID];
__device__ float g_pool[N_GRAPHS * HID];          // zeroed by final_kernel after use
__device__ int   g_is64;

__device__ __align__(16) int g_cnt_i[N_NODES];    // zeroed by fused kernel after scan
__device__ int g_rowstart[N_NODES + 1];
__device__ int g_cursor[N_NODES];
__device__ unsigned long long g_pkt[SCAN_BLOCKS]; // zeroed by fused kernel after scan

struct __align__(8) Edge { int r; float w; };
__device__ Edge g_edges[N_EDGES];

// ---------------- f32x2 helpers ----------------
__device__ __forceinline__ unsigned long long pk2(float a, float b) {
    unsigned long long r;
    asm("mov.b64 %0, {%1, %2};" : "=l"(r) : "f"(a), "f"(b));
    return r;
}
__device__ __forceinline__ void fma2(unsigned long long& d,
                                     unsigned long long a, unsigned long long b) {
    asm("fma.rn.f32x2 %0, %1, %2, %0;" : "+l"(d) : "l"(a), "l"(b));
}
__device__ __forceinline__ float2 upk2(unsigned long long v) {
    float2 f;
    asm("mov.b64 {%0, %1}, %2;" : "=f"(f.x), "=f"(f.y) : "l"(v));
    return f;
}

// ---------------- index dtype helper ----------------
__device__ __forceinline__ long long ld_idx(const void* p, long long i, int is64) {
    if (is64) return ((const long long*)p)[i];
    return (long long)((const int*)p)[i];
}

__device__ __forceinline__ void ld_idx4(const void* p, long long base_elem, int is64, int out[4]) {
    if (is64) {
        const longlong2* q = (const longlong2*)((const long long*)p + base_elem);
        longlong2 a = q[0];
        longlong2 b = q[1];
        out[0] = (int)a.x; out[1] = (int)a.y; out[2] = (int)b.x; out[3] = (int)b.y;
    } else {
        int4 a = *(const int4*)((const int*)p + base_elem);
        out[0] = a.x; out[1] = a.y; out[2] = a.z; out[3] = a.w;
    }
}

// ---------------- 0: in-degree count (+local is64 detect; cnt_i pre-zeroed) ------
__global__ void __launch_bounds__(256) count_kernel(const void* ei) {
    __shared__ int s_is64;
    if (threadIdx.x < 32) {
        const long long* p = (const long long*)ei;
        long long v = p[threadIdx.x];
        unsigned ok = __ballot_sync(0xffffffffu, v >= 0 && v < N_NODES);
        if (threadIdx.x == 0) s_is64 = (ok == 0xffffffffu) ? 1 : 0;
    }
    __syncthreads();
    int is64 = s_is64;
    if (blockIdx.x == 0 && threadIdx.x == 0) {
        g_is64 = is64;
        g_rowstart[N_NODES] = N_EDGES;
    }
    int base = (blockIdx.x * blockDim.x + threadIdx.x) * 4;
    if (base >= N_EDGES) return;
    int c[4];
    ld_idx4(ei, (long long)N_EDGES + base, is64, c);
    #pragma unroll
    for (int q = 0; q < 4; q++) atomicAdd(&g_cnt_i[c[q]], 1);
}

// ---------------- 1: exclusive scan (decoupled lookback; pkt pre-zeroed) + dinv ---
__global__ void __launch_bounds__(256) scan_kernel() {
    __shared__ int sh[256];
    __shared__ int s_prefix;
    int t = threadIdx.x;
    int b = blockIdx.x;
    int i = b * 256 + t;
    int v = (i < N_NODES) ? g_cnt_i[i] : 0;

    sh[t] = v;
    __syncthreads();
    #pragma unroll
    for (int s = 1; s < 256; s <<= 1) {
        int a = (t >= s) ? sh[t - s] : 0;
        __syncthreads();
        sh[t] += a;
        __syncthreads();
    }
    int incl = sh[t];
    int agg = sh[255];

    if (t == 0) {
        __threadfence();
        atomicExch(&g_pkt[b], (1ull << 32) | (unsigned long long)(unsigned)agg);
    }

    if (t < 32) {
        int prefix = 0;
        int idx = b - 1;
        while (idx >= 0) {
            int look = idx - t;
            unsigned long long pkt = 0ull;
            if (look >= 0) {
                do { pkt = atomicAdd(&g_pkt[look], 0ull); } while ((pkt >> 32) == 0ull);
            }
            unsigned incmask = __ballot_sync(0xffffffffu, look >= 0 && (pkt >> 32) == 2ull);
            int val = (int)(unsigned)pkt;
            if (incmask) {
                int firstinc = __ffs(incmask) - 1;
                int contrib = (t <= firstinc) ? val : 0;
                #pragma unroll
                for (int o = 16; o; o >>= 1) contrib += __shfl_down_sync(0xffffffffu, contrib, o);
                prefix += __shfl_sync(0xffffffffu, contrib, 0);
                break;
            } else {
                int contrib = (look >= 0) ? val : 0;
                #pragma unroll
                for (int o = 16; o; o >>= 1) contrib += __shfl_down_sync(0xffffffffu, contrib, o);
                prefix += __shfl_sync(0xffffffffu, contrib, 0);
                idx -= 32;
            }
        }
        if (t == 0) {
            s_prefix = prefix;
            __threadfence();
            atomicExch(&g_pkt[b], (2ull << 32) | (unsigned long long)(unsigned)(prefix + agg));
        }
    }
    __syncthreads();
    int prefix = s_prefix;

    if (i < N_NODES) {
        int start = prefix + incl - v;
        g_rowstart[i] = start;
        g_cursor[i] = start;
        g_dinv[i] = rsqrtf((float)v + 1.0f);
    }
}

// ---------------- 2: fill CSR ----------------
__global__ void __launch_bounds__(256) fill_kernel(const void* ei) {
    int base = (blockIdx.x * blockDim.x + threadIdx.x) * 4;
    if (base >= N_EDGES) return;
    int is64 = g_is64;
    int r[4], c[4];
    ld_idx4(ei, base, is64, r);
    ld_idx4(ei, (long long)N_EDGES + base, is64, c);
    float dr[4], dc[4];
    #pragma unroll
    for (int q = 0; q < 4; q++) { dr[q] = g_dinv[r[q]]; dc[q] = g_dinv[c[q]]; }
    int pos[4];
    #pragma unroll
    for (int q = 0; q < 4; q++) pos[q] = atomicAdd(&g_cursor[c[q]], 1);
    #pragma unroll
    for (int q = 0; q < 4; q++) {
        Edge ed; ed.r = r[q]; ed.w = dr[q] * dc[q];
        g_edges[pos[q]] = ed;
    }
}

// ---------------- GEMM1 (K=128): single smem phase — R12 measured 40.1us ----------
__global__ void __launch_bounds__(256, 2) gemm1_kernel(
        const float* __restrict__ X, const float* __restrict__ W,
        float* __restrict__ Y, int n) {
    extern __shared__ float sm[];
    float* Ws = sm;                 // 128*64
    float* Xs = sm + 128 * 64;      // 128*128
    int t = threadIdx.x;
    int row0 = blockIdx.x * 128;
    int c0 = (t & 15) * 4;
    int r0 = (t >> 4) * 8;

    #pragma unroll
    for (int i = 0; i < 8; i++) {
        int idx = t + i * 256;
        ((float4*)Ws)[idx] = ((const float4*)W)[idx];
    }
    #pragma unroll
    for (int i = 0; i < 16; i++) {
        int idx = t + i * 256;
        int r = idx >> 5, kq = idx & 31;
        int gr = row0 + r;
        float4 v = (gr < n) ? ((const float4*)(X + (size_t)gr * 128))[kq]
                            : make_float4(0.f, 0.f, 0.f, 0.f);
        ((float4*)Xs)[idx] = v;
    }
    __syncthreads();

    unsigned long long a01[8], a23[8];
    #pragma unroll
    for (int r = 0; r < 8; r++) { a01[r] = 0ull; a23[r] = 0ull; }

    #pragma unroll 4
    for (int k = 0; k < 128; k += 4) {
        float4 xv[8];
        #pragma unroll
        for (int r = 0; r < 8; r++) xv[r] = *(const float4*)&Xs[(r0 + r) * 128 + k];
        #pragma unroll
        for (int kk = 0; kk < 4; kk++) {
            float4 wv = *(const float4*)&Ws[(k + kk) * 64 + c0];
            unsigned long long w01 = pk2(wv.x, wv.y);
            unsigned long long w23 = pk2(wv.z, wv.w);
            #pragma unroll
            for (int r = 0; r < 8; r++) {
                float xs = kk == 0 ? xv[r].x : kk == 1 ? xv[r].y : kk == 2 ? xv[r].z : xv[r].w;
                unsigned long long x2 = pk2(xs, xs);
                fma2(a01[r], x2, w01);
                fma2(a23[r], x2, w23);
            }
        }
    }

    #pragma unroll
    for (int r = 0; r < 8; r++) {
        int gr = row0 + r0 + r;
        if (gr < n) {
            float2 lo = upk2(a01[r]);
            float2 hi = upk2(a23[r]);
            float4 o; o.x = lo.x; o.y = lo.y; o.z = hi.x; o.w = hi.y;
            *(float4*)&Y[(size_t)gr * 64 + c0] = o;
        }
    }
}

// ---------------- gather core ----------------
__device__ __forceinline__ float4 gather_node4(const float* __restrict__ xw,
                                               const float* __restrict__ bias,
                                               int node, int c4) {
    int s = g_rowstart[node];
    int e = g_rowstart[node + 1];
    float dc = g_dinv[node];

    float4 sv = *(const float4*)&xw[(size_t)node * 64 + c4 * 4];
    float sl = dc * dc;
    unsigned long long a01 = pk2(sv.x * sl, sv.y * sl);
    unsigned long long a23 = pk2(sv.z * sl, sv.w * sl);
    unsigned long long b01 = 0ull, b23 = 0ull;

    int j = s;
    for (; j + 4 <= e; j += 4) {
        Edge ed[4];
        #pragma unroll
        for (int q = 0; q < 4; q++) ed[q] = g_edges[j + q];
        float4 v[4];
        #pragma unroll
        for (int q = 0; q < 4; q++)
            v[q] = *(const float4*)&xw[(size_t)ed[q].r * 64 + c4 * 4];
        #pragma unroll
        for (int q = 0; q < 4; q += 2) {
            unsigned long long w0 = pk2(ed[q].w, ed[q].w);
            unsigned long long w1 = pk2(ed[q + 1].w, ed[q + 1].w);
            fma2(a01, pk2(v[q].x,     v[q].y),     w0);
            fma2(a23, pk2(v[q].z,     v[q].w),     w0);
            fma2(b01, pk2(v[q + 1].x, v[q + 1].y), w1);
            fma2(b23, pk2(v[q + 1].z, v[q + 1].w), w1);
        }
    }
    for (; j < e; j++) {
        Edge e0 = g_edges[j];
        float4 v0 = *(const float4*)&xw[(size_t)e0.r * 64 + c4 * 4];
        unsigned long long w0 = pk2(e0.w, e0.w);
        fma2(a01, pk2(v0.x, v0.y), w0);
        fma2(a23, pk2(v0.z, v0.w), w0);
    }

    float2 p01 = upk2(a01), q01 = upk2(b01);
    float2 p23 = upk2(a23), q23 = upk2(b23);
    float4 bv = ((const float4*)bias)[c4];
    float4 r;
    r.x = fmaxf(p01.x + q01.x + bv.x, 0.f);
    r.y = fmaxf(p01.y + q01.y + bv.y, 0.f);
    r.z = fmaxf(p23.x + q23.x + bv.z, 0.f);
    r.w = fmaxf(p23.y + q23.y + bv.w, 0.f);
    return r;
}

// ---------------- FUSED: gather1(b1,relu) -> smem -> GEMM2(W2) -> g_h -------------
// Gather phase fills the 128x64 Xs tile in smem (no h round-trip), then the
// proven 8x4 GEMM inner loop runs from smem. Also state-cycles cnt_i/pkt.
__global__ void __launch_bounds__(256, 3) gather_gemm2_kernel(
        const float* __restrict__ xw, const float* __restrict__ b1,
        const float* __restrict__ W2, float* __restrict__ Y, int n) {
    __shared__ float Ws[64 * 64];
    __shared__ float Xs[128 * 64];
    int t = threadIdx.x;
    int row0 = blockIdx.x * 128;

    // state-cycle zeroing (cnt_i / pkt are dead after scan; reset for next replay)
    int gid = blockIdx.x * 256 + t;
    if (gid < 25000) ((int4*)g_cnt_i)[gid] = make_int4(0, 0, 0, 0);
    else if (gid - 25000 < SCAN_BLOCKS) g_pkt[gid - 25000] = 0ull;

    // load W2 while gathers are in flight later
    for (int i = t; i < 64 * 16; i += 256)
        ((float4*)Ws)[i] = ((const float4*)W2)[i];

    // gather phase: 8 warps x 2 nodes x 8 iters = 128 nodes
    {
        int w = t >> 5, lane = t & 31, c4g = lane & 15;
        #pragma unroll
        for (int it = 0; it < 8; it++) {
            int nl = it * 16 + w * 2 + (lane >> 4);
            int node = row0 + nl;
            if (node < n) {
                float4 r = gather_node4(xw, b1, node, c4g);
                *(float4*)&Xs[nl * 64 + c4g * 4] = r;
            }
        }
    }
    __syncthreads();

    // GEMM phase (identical shape to the measured gemm2)
    int c0 = (t & 15) * 4;
    int r0 = (t >> 4) * 8;
    unsigned long long a01[8], a23[8];
    #pragma unroll
    for (int r = 0; r < 8; r++) { a01[r] = 0ull; a23[r] = 0ull; }

    #pragma unroll 4
    for (int k = 0; k < 64; k += 4) {
        float4 xv[8];
        #pragma unroll
        for (int r = 0; r < 8; r++) xv[r] = *(const float4*)&Xs[(r0 + r) * 64 + k];
        #pragma unroll
        for (int kk = 0; kk < 4; kk++) {
            float4 wv = *(const float4*)&Ws[(k + kk) * 64 + c0];
            unsigned long long w01 = pk2(wv.x, wv.y);
            unsigned long long w23 = pk2(wv.z, wv.w);
            #pragma unroll
            for (int r = 0; r < 8; r++) {
                float xs = kk == 0 ? xv[r].x : kk == 1 ? xv[r].y : kk == 2 ? xv[r].z : xv[r].w;
                unsigned long long x2 = pk2(xs, xs);
                fma2(a01[r], x2, w01);
                fma2(a23[r], x2, w23);
            }
        }
    }

    #pragma unroll
    for (int r = 0; r < 8; r++) {
        int gr = row0 + r0 + r;
        if (gr < n) {
            float2 lo = upk2(a01[r]);
            float2 hi = upk2(a23[r]);
            float4 o; o.x = lo.x; o.y = lo.y; o.z = hi.x; o.w = hi.y;
            *(float4*)&Y[(size_t)gr * 64 + c0] = o;
        }
    }
}

// ---------------- gather2 + mean-pool ----------------
__global__ void gather_pool_kernel(const float* __restrict__ xw, const float* __restrict__ bias,
                                   const void* batch) {
    int gid = blockIdx.x * blockDim.x + threadIdx.x;
    int lane = threadIdx.x & 31;
    int node = (gid >> 5) * 2 + (lane >> 4);
    if (node >= N_NODES) return;
    int c4 = lane & 15;
    float4 r = gather_node4(xw, bias, node, c4);
    int g = (int)ld_idx(batch, node, g_is64);
    float* dst = &g_pool[g * HID + c4 * 4];
    asm volatile("red.global.add.v4.f32 [%0], {%1,%2,%3,%4};"
                 :: "l"(dst), "f"(r.x), "f"(r.y), "f"(r.z), "f"(r.w) : "memory");
}

// ---------------- final classifier (+re-zero pool for next replay) ----------------
__global__ void final_kernel(const float* __restrict__ Wl, const float* __restrict__ bl,
                             const void* batch, float* __restrict__ out) {
    __shared__ float s_inv;
    int g = blockIdx.x;
    int o = threadIdx.x;
    if (o == 0) {
        int is64 = g_is64;
        int lo0 = 0, hi0 = N_NODES;
        while (lo0 < hi0) { int m = (lo0 + hi0) >> 1;
            if (ld_idx(batch, m, is64) < g) lo0 = m + 1; else hi0 = m; }
        int lo1 = lo0, hi1 = N_NODES;
        while (lo1 < hi1) { int m = (lo1 + hi1) >> 1;
            if (ld_idx(batch, m, is64) < g + 1) lo1 = m + 1; else hi1 = m; }
        float cnt = (float)(lo1 - lo0);
        s_inv = 1.0f / fmaxf(cnt, 1.0f);
    }
    __syncthreads();
    if (o < OUT_CH) {
        float s = 0.0f;
        #pragma unroll
        for (int c = 0; c < HID; c++)
            s += g_pool[g * HID + c] * Wl[c * OUT_CH + o];
        out[g * OUT_CH + o] = s * s_inv + bl[o];
    }
    __syncthreads();
    g_pool[g * HID + o] = 0.0f;
}

// ---------------- launch ----------------
static cudaStream_t s_side = nullptr;
static cudaEvent_t  s_evFork = nullptr;
static cudaEvent_t  s_evJoin = nullptr;

extern "C" void kernel_launch(void* const* d_in, const int* in_sizes, int n_in,
                              void* d_out, int out_size) {
    const float* x  = (const float*)d_in[0];
    const float* W1 = (const float*)d_in[1];
    const float* b1 = (const float*)d_in[2];
    const float* W2 = (const float*)d_in[3];
    const float* b2 = (const float*)d_in[4];
    const float* Wl = (const float*)d_in[5];
    const float* bl = (const float*)d_in[6];
    const void*  ei = d_in[7];
    const void*  batch = d_in[8];
    float* out = (float*)d_out;

    if (!s_side) {
        int lo, hi;
        cudaDeviceGetStreamPriorityRange(&lo, &hi);
        cudaStreamCreateWithPriority(&s_side, cudaStreamNonBlocking, hi);
        cudaEventCreateWithFlags(&s_evFork, cudaEventDisableTiming);
        cudaEventCreateWithFlags(&s_evJoin, cudaEventDisableTiming);
        cudaFuncSetAttribute(gemm1_kernel,
                             cudaFuncAttributeMaxDynamicSharedMemorySize, 96 * 1024);
    }

    float *xw = nullptr, *h = nullptr;
    cudaGetSymbolAddress((void**)&xw, g_xw);
    cudaGetSymbolAddress((void**)&h,  g_h);

    const int T = 256;
    int nb_edges4 = (N_EDGES / 4 + T - 1) / T;
    int nb_gemm   = (N_NODES + 127) / 128;
    int nb_gather = ((N_NODES + 1) / 2 * 32 + T - 1) / T;

    // fork: build on side stream (tail-overlaps gemm1), gemm1 on main
    cudaEventRecord(s_evFork, 0);
    cudaStreamWaitEvent(s_side, s_evFork, 0);

    count_kernel<<<nb_edges4, T, 0, s_side>>>(ei);            // 0
    scan_kernel<<<SCAN_BLOCKS, T, 0, s_side>>>();             // 1
    fill_kernel<<<nb_edges4, T, 0, s_side>>>(ei);             // 2
    cudaEventRecord(s_evJoin, s_side);

    gemm1_kernel<<<nb_gemm, T, 96 * 1024>>>(x, W1, xw, N_NODES);  // 3

    cudaStreamWaitEvent(0, s_evJoin, 0);
    gather_gemm2_kernel<<<nb_gemm, T>>>(xw, b1, W2, h, N_NODES);  // 4 (fused)
    gather_pool_kernel<<<nb_gather, T>>>(h, b2, batch);           // 5
    final_kernel<<<N_GRAPHS, 64>>>(Wl, bl, batch, out);           // 6
}